// round 1
// baseline (speedup 1.0000x reference)
#include <cuda_runtime.h>

#define NN 100000
#define FEAT 128

typedef unsigned long long u64;

// ---------------- device scratch (no allocs allowed) ----------------
__device__ float g_msg[(size_t)NN * FEAT];   // 51.2 MB scatter accumulator
__device__ float g_h[(size_t)NN * FEAT];     // 51.2 MB hidden activations
__device__ float g_deg[NN];
__device__ float g_scale[NN];

// ---------------- zero kernels (hard-wired to globals) ----------------
__global__ void zero_msg_kernel() {
    size_t n4 = (size_t)NN * FEAT / 4;
    size_t i = (size_t)blockIdx.x * blockDim.x + threadIdx.x;
    size_t stride = (size_t)gridDim.x * blockDim.x;
    float4 z = make_float4(0.f, 0.f, 0.f, 0.f);
    float4* p = (float4*)g_msg;
    for (; i < n4; i += stride) p[i] = z;
}

__global__ void zero_deg_kernel(int n) {
    int i = blockIdx.x * blockDim.x + threadIdx.x;
    if (i < n) g_deg[i] = 0.f;
}

// ---------------- scatter: warp per edge, vector red ----------------
__global__ void scatter_kernel(const float* __restrict__ feat,
                               const int* __restrict__ src,
                               const int* __restrict__ dst,
                               int nE, int withDeg) {
    int gw = (int)(((size_t)blockIdx.x * blockDim.x + threadIdx.x) >> 5);
    int lane = threadIdx.x & 31;
    if (gw >= nE) return;
    int s = __ldg(src + gw);
    int d = __ldg(dst + gw);
    float4 v = __ldg((const float4*)(feat + (size_t)s * FEAT) + lane);
    float* out = g_msg + (size_t)d * FEAT + lane * 4;
    asm volatile("red.global.add.v4.f32 [%0], {%1,%2,%3,%4};"
                 :: "l"(out), "f"(v.x), "f"(v.y), "f"(v.z), "f"(v.w) : "memory");
    if (withDeg && lane == 0) atomicAdd(&g_deg[d], 1.0f);
}

__global__ void invdeg_kernel(int n) {
    int i = blockIdx.x * blockDim.x + threadIdx.x;
    if (i < n) g_scale[i] = 1.0f / fmaxf(g_deg[i], 1.0f);
}

// ---------------- fused SAGE layer GEMM ----------------
// OUT[row] = relu( X[row] @ Wself + (g_msg[row]*g_scale[row]) @ Wneigh + b )
// Packed-f32x2 FMA path (fma.rn.f32x2 only reachable via PTX on sm_103a).

__device__ __forceinline__ void fma2(u64& d, u64 a, u64 b) {
    asm("fma.rn.f32x2 %0, %1, %2, %0;" : "+l"(d) : "l"(a), "l"(b));
}
__device__ __forceinline__ u64 dup2(float x) {
    u64 r; asm("mov.b64 %0, {%1, %1};" : "=l"(r) : "f"(x)); return r;
}
__device__ __forceinline__ void unpack2(u64 v, float& lo, float& hi) {
    asm("mov.b64 {%0, %1}, %2;" : "=f"(lo), "=f"(hi) : "l"(v));
}

#define BR 64            // rows per block
#define IN_STRIDE 68     // padded transposed-input stride (keeps 16B align, kills conflicts)
#define GEMM_SMEM_BYTES ((64 * 128 + 64 * IN_STRIDE) * 4)

extern __shared__ float smem[];

__global__ __launch_bounds__(256)
void sage_gemm_kernel(const float* __restrict__ X,
                      const float* __restrict__ Wself,
                      const float* __restrict__ Wneigh,
                      const float* __restrict__ bias,
                      float* __restrict__ OUT, int n) {
    float* sW  = smem;               // [64][128] weight chunk
    float* sIn = smem + 64 * 128;    // [64][IN_STRIDE] transposed input chunk: [k][row]

    const int tid = threadIdx.x;
    const int rg = tid >> 4;         // row group 0..15  -> rows rg*4..rg*4+3
    const int cg = tid & 15;         // col group 0..15  -> cols cg*8..cg*8+7
    const int row0 = blockIdx.x * BR;

    u64 acc[4][4];
#pragma unroll
    for (int r = 0; r < 4; r++)
#pragma unroll
        for (int j = 0; j < 4; j++) acc[r][j] = 0ull;

    for (int kc = 0; kc < 4; kc++) {
        // ---- stage input chunk (transposed) ----
        {
            const float* srcp = (kc < 2) ? X : g_msg;
            int r  = tid >> 2;            // 0..63 local row
            int c4 = tid & 3;
            int grow = row0 + r;
            bool ok = grow < n;
            float sc = 1.0f;
            if (kc >= 2 && ok) sc = g_scale[grow];
#pragma unroll
            for (int j = 0; j < 4; j++) {
                int kl = c4 * 16 + j * 4;   // local k of this float4
                float4 v = make_float4(0.f, 0.f, 0.f, 0.f);
                if (ok) v = __ldg((const float4*)(srcp + (size_t)grow * FEAT + (kc & 1) * 64 + kl));
                if (kc >= 2) { v.x *= sc; v.y *= sc; v.z *= sc; v.w *= sc; }
                sIn[(kl + 0) * IN_STRIDE + r] = v.x;
                sIn[(kl + 1) * IN_STRIDE + r] = v.y;
                sIn[(kl + 2) * IN_STRIDE + r] = v.z;
                sIn[(kl + 3) * IN_STRIDE + r] = v.w;
            }
            // ---- stage weight chunk (rows (kc&1)*64 .. +63 of the right matrix) ----
            const float* wp = (kc < 2) ? Wself : Wneigh;
            int krow0 = (kc & 1) * 64;
#pragma unroll
            for (int j = 0; j < 8; j++) {
                int idx = j * 256 + tid;        // 0..2047 float4s
                int kl = idx >> 5;
                int c  = (idx & 31) * 4;
                *(float4*)(sW + kl * 128 + c) =
                    __ldg((const float4*)(wp + (size_t)(krow0 + kl) * FEAT + c));
            }
        }
        __syncthreads();

#pragma unroll 8
        for (int k = 0; k < 64; k++) {
            float4 a = *(const float4*)(sIn + k * IN_STRIDE + rg * 4);
            u64 pa0 = dup2(a.x), pa1 = dup2(a.y), pa2 = dup2(a.z), pa3 = dup2(a.w);
            const u64* pw = (const u64*)(sW + k * 128 + cg * 8);
            u64 b0 = pw[0], b1 = pw[1], b2 = pw[2], b3 = pw[3];
            fma2(acc[0][0], pa0, b0); fma2(acc[0][1], pa0, b1); fma2(acc[0][2], pa0, b2); fma2(acc[0][3], pa0, b3);
            fma2(acc[1][0], pa1, b0); fma2(acc[1][1], pa1, b1); fma2(acc[1][2], pa1, b2); fma2(acc[1][3], pa1, b3);
            fma2(acc[2][0], pa2, b0); fma2(acc[2][1], pa2, b1); fma2(acc[2][2], pa2, b2); fma2(acc[2][3], pa2, b3);
            fma2(acc[3][0], pa3, b0); fma2(acc[3][1], pa3, b1); fma2(acc[3][2], pa3, b2); fma2(acc[3][3], pa3, b3);
        }
        __syncthreads();
    }

    // ---- epilogue: bias + relu + store ----
    float bv[8];
#pragma unroll
    for (int i = 0; i < 8; i++) bv[i] = __ldg(bias + cg * 8 + i);
#pragma unroll
    for (int r = 0; r < 4; r++) {
        int grow = row0 + rg * 4 + r;
        if (grow >= n) continue;
        float o[8];
#pragma unroll
        for (int j = 0; j < 4; j++) unpack2(acc[r][j], o[2 * j], o[2 * j + 1]);
#pragma unroll
        for (int i = 0; i < 8; i++) o[i] = fmaxf(o[i] + bv[i], 0.0f);
        float4* dst4 = (float4*)(OUT + (size_t)grow * FEAT + cg * 8);
        dst4[0] = make_float4(o[0], o[1], o[2], o[3]);
        dst4[1] = make_float4(o[4], o[5], o[6], o[7]);
    }
}

// ---------------- final projection: warp per node, 128 -> 2 ----------------
__global__ void final_kernel(const float* __restrict__ Wf,
                             const float* __restrict__ bf,
                             float* __restrict__ out, int n) {
    int gw = (int)(((size_t)blockIdx.x * blockDim.x + threadIdx.x) >> 5);
    int lane = threadIdx.x & 31;
    if (gw >= n) return;
    float4 h = __ldg((const float4*)(g_h + (size_t)gw * FEAT) + lane);
    float s0 = 0.f, s1 = 0.f;
    const float* hv = (const float*)&h;
#pragma unroll
    for (int i = 0; i < 4; i++) {
        float2 w = __ldg((const float2*)Wf + lane * 4 + i);
        s0 += hv[i] * w.x;
        s1 += hv[i] * w.y;
    }
#pragma unroll
    for (int off = 16; off; off >>= 1) {
        s0 += __shfl_down_sync(0xffffffffu, s0, off);
        s1 += __shfl_down_sync(0xffffffffu, s1, off);
    }
    if (lane == 0) {
        out[2 * (size_t)gw]     = s0 + __ldg(bf);
        out[2 * (size_t)gw + 1] = s1 + __ldg(bf + 1);
    }
}

// ---------------- launch ----------------
extern "C" void kernel_launch(void* const* d_in, const int* in_sizes, int n_in,
                              void* d_out, int out_size) {
    const float* x   = (const float*)d_in[0];
    const float* Ws1 = (const float*)d_in[1];
    const float* Wn1 = (const float*)d_in[2];
    const float* b1  = (const float*)d_in[3];
    const float* Ws2 = (const float*)d_in[4];
    const float* Wn2 = (const float*)d_in[5];
    const float* b2  = (const float*)d_in[6];
    const float* Wf  = (const float*)d_in[7];
    const float* bf  = (const float*)d_in[8];
    const int*   src = (const int*)d_in[9];
    const int*   dst = (const int*)d_in[10];
    float* out = (float*)d_out;

    int n  = in_sizes[0] / FEAT;
    int nE = in_sizes[9];

    cudaFuncSetAttribute(sage_gemm_kernel,
                         cudaFuncAttributeMaxDynamicSharedMemorySize, GEMM_SMEM_BYTES);

    void* p_h = 0;
    cudaGetSymbolAddress(&p_h, g_h);
    float* h = (float*)p_h;

    int scatterBlocks = (nE + 7) / 8;                 // 8 warps/block, warp per edge
    int gemmBlocks    = (n + BR - 1) / BR;

    // layer 1
    zero_msg_kernel<<<2048, 256>>>();
    zero_deg_kernel<<<(n + 255) / 256, 256>>>(n);
    scatter_kernel<<<scatterBlocks, 256>>>(x, src, dst, nE, 1);
    invdeg_kernel<<<(n + 255) / 256, 256>>>(n);
    sage_gemm_kernel<<<gemmBlocks, 256, GEMM_SMEM_BYTES>>>(x, Ws1, Wn1, b1, h, n);

    // layer 2
    zero_msg_kernel<<<2048, 256>>>();
    scatter_kernel<<<scatterBlocks, 256>>>(h, src, dst, nE, 0);
    sage_gemm_kernel<<<gemmBlocks, 256, GEMM_SMEM_BYTES>>>(h, Ws2, Wn2, b2, h, n);

    // final projection
    final_kernel<<<(n + 7) / 8, 256>>>(Wf, bf, out, n);
}

// round 2
// speedup vs baseline: 1.4031x; 1.4031x over previous
#include <cuda_runtime.h>

#define NN 100000
#define MAXE 1600000
#define FEAT 128
#define SCANB 1024

typedef unsigned long long u64;

// ---------------- device scratch (no allocs allowed) ----------------
__device__ float g_msg[(size_t)NN * FEAT];   // 51.2 MB aggregated (mean) features
__device__ float g_h[(size_t)NN * FEAT];     // 51.2 MB hidden activations
__device__ int   g_cnt[NN];
__device__ int   g_scanTmp[NN];
__device__ int   g_rowptr[NN + 1];
__device__ int   g_cursor[NN];
__device__ int   g_col[MAXE];
__device__ int   g_bsum[(NN + SCANB - 1) / SCANB];
__device__ int   g_boff[(NN + SCANB - 1) / SCANB];

// ================= CSR build =================
__global__ void zero_cnt_kernel(int n) {
    int i = blockIdx.x * blockDim.x + threadIdx.x;
    if (i < n) g_cnt[i] = 0;
}

__global__ void hist_kernel(const int* __restrict__ dst, int nE) {
    int i = blockIdx.x * blockDim.x + threadIdx.x;
    if (i < nE) atomicAdd(&g_cnt[__ldg(dst + i)], 1);
}

// per-block inclusive scan (Hillis-Steele), block totals to g_bsum
__global__ void scan1_kernel(int n) {
    __shared__ int sh[SCANB];
    int i = blockIdx.x * SCANB + threadIdx.x;
    int v = (i < n) ? g_cnt[i] : 0;
    sh[threadIdx.x] = v;
    __syncthreads();
#pragma unroll
    for (int off = 1; off < SCANB; off <<= 1) {
        int t = (threadIdx.x >= off) ? sh[threadIdx.x - off] : 0;
        __syncthreads();
        sh[threadIdx.x] += t;
        __syncthreads();
    }
    if (i < n) g_scanTmp[i] = sh[threadIdx.x];
    if (threadIdx.x == SCANB - 1) g_bsum[blockIdx.x] = sh[SCANB - 1];
}

// single-block exclusive scan of block sums
__global__ void scan2_kernel(int nb) {
    __shared__ int sh[SCANB];
    int v = (threadIdx.x < nb) ? g_bsum[threadIdx.x] : 0;
    sh[threadIdx.x] = v;
    __syncthreads();
#pragma unroll
    for (int off = 1; off < SCANB; off <<= 1) {
        int t = (threadIdx.x >= off) ? sh[threadIdx.x - off] : 0;
        __syncthreads();
        sh[threadIdx.x] += t;
        __syncthreads();
    }
    if (threadIdx.x < nb) g_boff[threadIdx.x] = sh[threadIdx.x] - v;  // exclusive
}

// rowptr[i] = exclusive prefix; also init cursor
__global__ void scan3_kernel(int n) {
    int i = blockIdx.x * blockDim.x + threadIdx.x;
    if (i > n) return;
    int v = (i == 0) ? 0 : (g_scanTmp[i - 1] + g_boff[(i - 1) / SCANB]);
    g_rowptr[i] = v;
    if (i < n) g_cursor[i] = v;
}

__global__ void fill_kernel(const int* __restrict__ src,
                            const int* __restrict__ dst, int nE) {
    int i = blockIdx.x * blockDim.x + threadIdx.x;
    if (i >= nE) return;
    int d = __ldg(dst + i);
    int pos = atomicAdd(&g_cursor[d], 1);
    g_col[pos] = __ldg(src + i);
}

// ================= gather-mean: warp per node =================
__global__ void gather_kernel(const float* __restrict__ feat, int n) {
    int gw = (int)(((size_t)blockIdx.x * blockDim.x + threadIdx.x) >> 5);
    int lane = threadIdx.x & 31;
    if (gw >= n) return;
    int beg = __ldg(g_rowptr + gw);
    int end = __ldg(g_rowptr + gw + 1);
    float4 acc = make_float4(0.f, 0.f, 0.f, 0.f);
    int i = beg;
    for (; i + 4 <= end; i += 4) {
        int s0 = __ldg(g_col + i);
        int s1 = __ldg(g_col + i + 1);
        int s2 = __ldg(g_col + i + 2);
        int s3 = __ldg(g_col + i + 3);
        float4 a = __ldg((const float4*)(feat + (size_t)s0 * FEAT) + lane);
        float4 b = __ldg((const float4*)(feat + (size_t)s1 * FEAT) + lane);
        float4 c = __ldg((const float4*)(feat + (size_t)s2 * FEAT) + lane);
        float4 d = __ldg((const float4*)(feat + (size_t)s3 * FEAT) + lane);
        acc.x += (a.x + b.x) + (c.x + d.x);
        acc.y += (a.y + b.y) + (c.y + d.y);
        acc.z += (a.z + b.z) + (c.z + d.z);
        acc.w += (a.w + b.w) + (c.w + d.w);
    }
    for (; i < end; i++) {
        int s0 = __ldg(g_col + i);
        float4 a = __ldg((const float4*)(feat + (size_t)s0 * FEAT) + lane);
        acc.x += a.x; acc.y += a.y; acc.z += a.z; acc.w += a.w;
    }
    float inv = 1.0f / (float)max(end - beg, 1);
    acc.x *= inv; acc.y *= inv; acc.z *= inv; acc.w *= inv;
    *((float4*)(g_msg + (size_t)gw * FEAT) + lane) = acc;
}

// ================= fused SAGE layer GEMM (packed f32x2 FMA) =================
__device__ __forceinline__ void fma2(u64& d, u64 a, u64 b) {
    asm("fma.rn.f32x2 %0, %1, %2, %0;" : "+l"(d) : "l"(a), "l"(b));
}
__device__ __forceinline__ u64 dup2(float x) {
    u64 r; asm("mov.b64 %0, {%1, %1};" : "=l"(r) : "f"(x)); return r;
}
__device__ __forceinline__ void unpack2(u64 v, float& lo, float& hi) {
    asm("mov.b64 {%0, %1}, %2;" : "=f"(lo), "=f"(hi) : "l"(v));
}

#define BR 64
#define IN_STRIDE 68
#define GEMM_SMEM_BYTES ((64 * 128 + 64 * IN_STRIDE) * 4)

extern __shared__ float smem[];

__global__ __launch_bounds__(256)
void sage_gemm_kernel(const float* __restrict__ X,
                      const float* __restrict__ Wself,
                      const float* __restrict__ Wneigh,
                      const float* __restrict__ bias,
                      float* __restrict__ OUT, int n) {
    float* sW  = smem;               // [64][128]
    float* sIn = smem + 64 * 128;    // [64][IN_STRIDE] transposed: [k][row]

    const int tid = threadIdx.x;
    const int rg = tid >> 4;
    const int cg = tid & 15;
    const int row0 = blockIdx.x * BR;

    u64 acc[4][4];
#pragma unroll
    for (int r = 0; r < 4; r++)
#pragma unroll
        for (int j = 0; j < 4; j++) acc[r][j] = 0ull;

    for (int kc = 0; kc < 4; kc++) {
        {
            const float* srcp = (kc < 2) ? X : g_msg;
            int r  = tid >> 2;
            int c4 = tid & 3;
            int grow = row0 + r;
            bool ok = grow < n;
#pragma unroll
            for (int j = 0; j < 4; j++) {
                int kl = c4 * 16 + j * 4;
                float4 v = make_float4(0.f, 0.f, 0.f, 0.f);
                if (ok) v = __ldg((const float4*)(srcp + (size_t)grow * FEAT + (kc & 1) * 64 + kl));
                sIn[(kl + 0) * IN_STRIDE + r] = v.x;
                sIn[(kl + 1) * IN_STRIDE + r] = v.y;
                sIn[(kl + 2) * IN_STRIDE + r] = v.z;
                sIn[(kl + 3) * IN_STRIDE + r] = v.w;
            }
            const float* wp = (kc < 2) ? Wself : Wneigh;
            int krow0 = (kc & 1) * 64;
#pragma unroll
            for (int j = 0; j < 8; j++) {
                int idx = j * 256 + tid;
                int kl = idx >> 5;
                int c  = (idx & 31) * 4;
                *(float4*)(sW + kl * 128 + c) =
                    __ldg((const float4*)(wp + (size_t)(krow0 + kl) * FEAT + c));
            }
        }
        __syncthreads();

#pragma unroll 8
        for (int k = 0; k < 64; k++) {
            float4 a = *(const float4*)(sIn + k * IN_STRIDE + rg * 4);
            u64 pa0 = dup2(a.x), pa1 = dup2(a.y), pa2 = dup2(a.z), pa3 = dup2(a.w);
            const u64* pw = (const u64*)(sW + k * 128 + cg * 8);
            u64 b0 = pw[0], b1 = pw[1], b2 = pw[2], b3 = pw[3];
            fma2(acc[0][0], pa0, b0); fma2(acc[0][1], pa0, b1); fma2(acc[0][2], pa0, b2); fma2(acc[0][3], pa0, b3);
            fma2(acc[1][0], pa1, b0); fma2(acc[1][1], pa1, b1); fma2(acc[1][2], pa1, b2); fma2(acc[1][3], pa1, b3);
            fma2(acc[2][0], pa2, b0); fma2(acc[2][1], pa2, b1); fma2(acc[2][2], pa2, b2); fma2(acc[2][3], pa2, b3);
            fma2(acc[3][0], pa3, b0); fma2(acc[3][1], pa3, b1); fma2(acc[3][2], pa3, b2); fma2(acc[3][3], pa3, b3);
        }
        __syncthreads();
    }

    float bv[8];
#pragma unroll
    for (int i = 0; i < 8; i++) bv[i] = __ldg(bias + cg * 8 + i);
#pragma unroll
    for (int r = 0; r < 4; r++) {
        int grow = row0 + rg * 4 + r;
        if (grow >= n) continue;
        float o[8];
#pragma unroll
        for (int j = 0; j < 4; j++) unpack2(acc[r][j], o[2 * j], o[2 * j + 1]);
#pragma unroll
        for (int i = 0; i < 8; i++) o[i] = fmaxf(o[i] + bv[i], 0.0f);
        float4* dst4 = (float4*)(OUT + (size_t)grow * FEAT + cg * 8);
        dst4[0] = make_float4(o[0], o[1], o[2], o[3]);
        dst4[1] = make_float4(o[4], o[5], o[6], o[7]);
    }
}

// ================= final projection: warp per node, 128 -> 2 =================
__global__ void final_kernel(const float* __restrict__ Wf,
                             const float* __restrict__ bf,
                             float* __restrict__ out, int n) {
    int gw = (int)(((size_t)blockIdx.x * blockDim.x + threadIdx.x) >> 5);
    int lane = threadIdx.x & 31;
    if (gw >= n) return;
    float4 h = __ldg((const float4*)(g_h + (size_t)gw * FEAT) + lane);
    float s0 = 0.f, s1 = 0.f;
    const float* hv = (const float*)&h;
#pragma unroll
    for (int i = 0; i < 4; i++) {
        float2 w = __ldg((const float2*)Wf + lane * 4 + i);
        s0 += hv[i] * w.x;
        s1 += hv[i] * w.y;
    }
#pragma unroll
    for (int off = 16; off; off >>= 1) {
        s0 += __shfl_down_sync(0xffffffffu, s0, off);
        s1 += __shfl_down_sync(0xffffffffu, s1, off);
    }
    if (lane == 0) {
        out[2 * (size_t)gw]     = s0 + __ldg(bf);
        out[2 * (size_t)gw + 1] = s1 + __ldg(bf + 1);
    }
}

// ================= launch =================
extern "C" void kernel_launch(void* const* d_in, const int* in_sizes, int n_in,
                              void* d_out, int out_size) {
    const float* x   = (const float*)d_in[0];
    const float* Ws1 = (const float*)d_in[1];
    const float* Wn1 = (const float*)d_in[2];
    const float* b1  = (const float*)d_in[3];
    const float* Ws2 = (const float*)d_in[4];
    const float* Wn2 = (const float*)d_in[5];
    const float* b2  = (const float*)d_in[6];
    const float* Wf  = (const float*)d_in[7];
    const float* bf  = (const float*)d_in[8];
    const int*   src = (const int*)d_in[9];
    const int*   dst = (const int*)d_in[10];
    float* out = (float*)d_out;

    int n  = in_sizes[0] / FEAT;
    int nE = in_sizes[9];
    int nb = (n + SCANB - 1) / SCANB;

    cudaFuncSetAttribute(sage_gemm_kernel,
                         cudaFuncAttributeMaxDynamicSharedMemorySize, GEMM_SMEM_BYTES);

    void* p_h = 0;
    cudaGetSymbolAddress(&p_h, g_h);
    float* h = (float*)p_h;

    // ---- CSR build (deterministic each call) ----
    zero_cnt_kernel<<<(n + 255) / 256, 256>>>(n);
    hist_kernel<<<(nE + 255) / 256, 256>>>(dst, nE);
    scan1_kernel<<<nb, SCANB>>>(n);
    scan2_kernel<<<1, SCANB>>>(nb);
    scan3_kernel<<<(n + 256) / 256, 256>>>(n);
    fill_kernel<<<(nE + 255) / 256, 256>>>(src, dst, nE);

    int gatherBlocks = (n + 7) / 8;   // 8 warps per block, warp per node
    int gemmBlocks   = (n + BR - 1) / BR;

    // layer 1
    gather_kernel<<<gatherBlocks, 256>>>(x, n);
    sage_gemm_kernel<<<gemmBlocks, 256, GEMM_SMEM_BYTES>>>(x, Ws1, Wn1, b1, h, n);

    // layer 2
    gather_kernel<<<gatherBlocks, 256>>>(h, n);
    sage_gemm_kernel<<<gemmBlocks, 256, GEMM_SMEM_BYTES>>>(h, Ws2, Wn2, b2, h, n);

    // final projection
    final_kernel<<<(n + 7) / 8, 256>>>(Wf, bf, out, n);
}